// round 10
// baseline (speedup 1.0000x reference)
#include <cuda_runtime.h>
#include <cuda_fp16.h>
#include <cstddef>

#define N_USERS 50000
#define N_ENT   100000
#define N_TOT   150000
#define D       64

// ---------------------------------------------------------------------------
// Scratch: y = x @ W in fp16 (sole consumer: edge pass), softmax denominator.
// ---------------------------------------------------------------------------
__device__ __align__(256) __half g_yh[(size_t)N_TOT * D];
__device__ float g_Z;

__global__ void init_z_kernel() { g_Z = 0.0f; }

// ---------------------------------------------------------------------------
// build: y = x @ W (fp32 math, fp16 store). Tile = 128 rows, 256 threads.
// ---------------------------------------------------------------------------
__global__ void __launch_bounds__(256) build_y_kernel(
    const int* __restrict__ uidx, const int* __restrict__ iidx,
    const float* __restrict__ ut, const float* __restrict__ et,
    const float* __restrict__ W)
{
    __shared__ float Ws[64 * 64];
    __shared__ float xst[64][128];

    const int tid = threadIdx.x;
    for (int i = tid; i < 1024; i += 256)
        ((float4*)Ws)[i] = ((const float4*)W)[i];

    const int row0 = blockIdx.x * 128;
    {
        const int lr = tid >> 1;
        const int lj = tid & 1;
        const int r  = row0 + lr;
        if (r < N_TOT) {
            const float* xrow;
            if (r < N_USERS) xrow = ut + (size_t)__ldg(uidx + r) * D;
            else             xrow = et + (size_t)__ldg(iidx + (r - N_USERS)) * D;
            #pragma unroll
            for (int i = 0; i < 8; i++) {
                const int c4 = lj * 8 + i;
                float4 v = ((const float4*)xrow)[c4];
                xst[c4 * 4 + 0][lr] = v.x;
                xst[c4 * 4 + 1][lr] = v.y;
                xst[c4 * 4 + 2][lr] = v.z;
                xst[c4 * 4 + 3][lr] = v.w;
            }
        }
    }
    __syncthreads();

    const int j  = tid & 15;
    const int rt = tid >> 4;

    float4 acc[8];
    #pragma unroll
    for (int r = 0; r < 8; r++) acc[r] = make_float4(0.f, 0.f, 0.f, 0.f);

    #pragma unroll 4
    for (int k = 0; k < 64; k++) {
        const float4 w  = *(const float4*)&Ws[k * 64 + j * 4];
        const float4 xa = *(const float4*)&xst[k][rt * 8];
        const float4 xb = *(const float4*)&xst[k][rt * 8 + 4];
        acc[0].x += xa.x * w.x; acc[0].y += xa.x * w.y; acc[0].z += xa.x * w.z; acc[0].w += xa.x * w.w;
        acc[1].x += xa.y * w.x; acc[1].y += xa.y * w.y; acc[1].z += xa.y * w.z; acc[1].w += xa.y * w.w;
        acc[2].x += xa.z * w.x; acc[2].y += xa.z * w.y; acc[2].z += xa.z * w.z; acc[2].w += xa.z * w.w;
        acc[3].x += xa.w * w.x; acc[3].y += xa.w * w.y; acc[3].z += xa.w * w.z; acc[3].w += xa.w * w.w;
        acc[4].x += xb.x * w.x; acc[4].y += xb.x * w.y; acc[4].z += xb.x * w.z; acc[4].w += xb.x * w.w;
        acc[5].x += xb.y * w.x; acc[5].y += xb.y * w.y; acc[5].z += xb.y * w.z; acc[5].w += xb.y * w.w;
        acc[6].x += xb.z * w.x; acc[6].y += xb.z * w.y; acc[6].z += xb.z * w.z; acc[6].w += xb.z * w.w;
        acc[7].x += xb.w * w.x; acc[7].y += xb.w * w.y; acc[7].z += xb.w * w.z; acc[7].w += xb.w * w.w;
    }

    #pragma unroll
    for (int r = 0; r < 8; r++) {
        const int row = row0 + rt * 8 + r;
        if (row < N_TOT) {
            __half2 h0 = __floats2half2_rn(acc[r].x, acc[r].y);
            __half2 h1 = __floats2half2_rn(acc[r].z, acc[r].w);
            uint2 u = make_uint2(*(unsigned*)&h0, *(unsigned*)&h1);
            ((uint2*)(g_yh + (size_t)row * D))[j] = u;
        }
    }
}

// ---------------------------------------------------------------------------
// Fused edge pass: 8 LANES PER EDGE (uint4 = 16B/lane covers the 128B fp16 row)
// -> 4 edges in flight per warp (2x gather MLP vs R9), 3-shuffle dot reduce.
// Output: two red.global.add.v4 per lane (same 256B/edge as before).
// ---------------------------------------------------------------------------
__global__ void __launch_bounds__(256) edge_kernel(
    const int* __restrict__ ei, int E, float* __restrict__ out)
{
    const int lane = threadIdx.x & 31;
    const int li   = lane & 7;                            // lane within 8-group
    const int grp  = lane >> 3;                           // 0..3
    const unsigned mask = 0xFFu << (grp * 8);
    const int gid  = (blockIdx.x * blockDim.x + threadIdx.x) >> 3;
    const int ng   = (gridDim.x * blockDim.x) >> 3;

    float zloc = 0.0f;

    for (int e = gid; e < E; e += ng) {
        const int src = __ldg(ei + e);
        const int dst = __ldg(ei + E + e);

        uint4 us = __ldg((const uint4*)(g_yh + (size_t)src * D) + li);
        uint4 ud = __ldg((const uint4*)(g_yh + (size_t)dst * D) + li);

        float2 s0 = __half22float2(*(__half2*)&us.x);
        float2 s1 = __half22float2(*(__half2*)&us.y);
        float2 s2 = __half22float2(*(__half2*)&us.z);
        float2 s3 = __half22float2(*(__half2*)&us.w);
        float2 d0 = __half22float2(*(__half2*)&ud.x);
        float2 d1 = __half22float2(*(__half2*)&ud.y);
        float2 d2 = __half22float2(*(__half2*)&ud.z);
        float2 d3 = __half22float2(*(__half2*)&ud.w);

        float t = s0.x * d0.x + s0.y * d0.y + s1.x * d1.x + s1.y * d1.y
                + s2.x * d2.x + s2.y * d2.y + s3.x * d3.x + s3.y * d3.y;
        t += __shfl_xor_sync(mask, t, 4);
        t += __shfl_xor_sync(mask, t, 2);
        t += __shfl_xor_sync(mask, t, 1);

        const float p = __expf(t >= 0.f ? t : 0.2f * t);   // leaky_relu(0.2)
        if (li == 0) zloc += p;

        float* dp = out + (size_t)dst * D + li * 8;
        asm volatile("red.global.add.v4.f32 [%0], {%1,%2,%3,%4};"
                     :: "l"(dp), "f"(p * s0.x), "f"(p * s0.y),
                        "f"(p * s1.x), "f"(p * s1.y)
                     : "memory");
        asm volatile("red.global.add.v4.f32 [%0], {%1,%2,%3,%4};"
                     :: "l"(dp + 4), "f"(p * s2.x), "f"(p * s2.y),
                        "f"(p * s3.x), "f"(p * s3.y)
                     : "memory");
    }

    // block-reduce zloc -> one atomic per block (loop done; full mask safe)
    float z = zloc;
    #pragma unroll
    for (int o = 16; o > 0; o >>= 1) z += __shfl_xor_sync(0xffffffffu, z, o);
    __shared__ float sz[8];
    if (lane == 0) sz[threadIdx.x >> 5] = z;
    __syncthreads();
    if (threadIdx.x == 0) {
        float s = 0.f;
        #pragma unroll
        for (int w = 0; w < 8; w++) s += sz[w];
        atomicAdd(&g_Z, s);
    }
}

// ---------------------------------------------------------------------------
// finalize: out = relu(out) / Z
// ---------------------------------------------------------------------------
__global__ void __launch_bounds__(256) finalize_kernel(float* __restrict__ out, int n)
{
    const float invZ = 1.0f / g_Z;
    const int n4 = n >> 2;
    float4* o4 = (float4*)out;
    const int st = gridDim.x * blockDim.x;
    for (int i = blockIdx.x * blockDim.x + threadIdx.x; i < n4; i += st) {
        float4 v = o4[i];
        v.x = v.x > 0.f ? v.x * invZ : 0.f;
        v.y = v.y > 0.f ? v.y * invZ : 0.f;
        v.z = v.z > 0.f ? v.z * invZ : 0.f;
        v.w = v.w > 0.f ? v.w * invZ : 0.f;
        o4[i] = v;
    }
}

// ---------------------------------------------------------------------------
// Launch: memset(out)+initZ on side stream ∥ build_y; join; edge; finalize.
// ---------------------------------------------------------------------------
extern "C" void kernel_launch(void* const* d_in, const int* in_sizes, int n_in,
                              void* d_out, int out_size)
{
    const int*   uidx = (const int*)d_in[0];
    const int*   iidx = (const int*)d_in[1];
    const int*   ei   = (const int*)d_in[2];
    const float* ut   = (const float*)d_in[5];
    const float* et   = (const float*)d_in[6];
    const float* W    = (const float*)d_in[7];
    float* out = (float*)d_out;
    const int E = in_sizes[2] / 2;

    static cudaStream_t s2 = nullptr;
    static cudaEvent_t ev_fork = nullptr, ev_join = nullptr;
    if (s2 == nullptr) {
        cudaStreamCreateWithFlags(&s2, cudaStreamNonBlocking);
        cudaEventCreateWithFlags(&ev_fork, cudaEventDisableTiming);
        cudaEventCreateWithFlags(&ev_join, cudaEventDisableTiming);
    }

    cudaEventRecord(ev_fork, 0);
    cudaStreamWaitEvent(s2, ev_fork, 0);
    cudaMemsetAsync(out, 0, (size_t)out_size * sizeof(float), s2);
    init_z_kernel<<<1, 1, 0, s2>>>();
    cudaEventRecord(ev_join, s2);

    build_y_kernel<<<(N_TOT + 127) / 128, 256>>>(uidx, iidx, ut, et, W);

    cudaStreamWaitEvent(0, ev_join, 0);
    edge_kernel<<<1184, 256>>>(ei, E, out);
    finalize_kernel<<<1184, 256>>>(out, out_size);
}

// round 11
// speedup vs baseline: 1.3261x; 1.3261x over previous
#include <cuda_runtime.h>
#include <cuda_fp16.h>
#include <cstddef>

#define N_USERS 50000
#define N_ENT   100000
#define N_TOT   150000
#define D       64

// ---------------------------------------------------------------------------
// Scratch: y = x @ W in fp16 (sole consumer: edge pass), softmax denominator.
// ---------------------------------------------------------------------------
__device__ __align__(256) __half g_yh[(size_t)N_TOT * D];
__device__ float g_Z;

// ---------------------------------------------------------------------------
// build: y = x @ W (fp32 math, fp16 store). Tile = 128 rows, 256 threads.
// Also zeroes g_Z (replaces the init_z launch).
// ---------------------------------------------------------------------------
__global__ void __launch_bounds__(256) build_y_kernel(
    const int* __restrict__ uidx, const int* __restrict__ iidx,
    const float* __restrict__ ut, const float* __restrict__ et,
    const float* __restrict__ W)
{
    __shared__ float Ws[64 * 64];
    __shared__ float xst[64][128];

    if (blockIdx.x == 0 && threadIdx.x == 0) g_Z = 0.0f;

    const int tid = threadIdx.x;
    for (int i = tid; i < 1024; i += 256)
        ((float4*)Ws)[i] = ((const float4*)W)[i];

    const int row0 = blockIdx.x * 128;
    {
        const int lr = tid >> 1;
        const int lj = tid & 1;
        const int r  = row0 + lr;
        if (r < N_TOT) {
            const float* xrow;
            if (r < N_USERS) xrow = ut + (size_t)__ldg(uidx + r) * D;
            else             xrow = et + (size_t)__ldg(iidx + (r - N_USERS)) * D;
            #pragma unroll
            for (int i = 0; i < 8; i++) {
                const int c4 = lj * 8 + i;
                float4 v = ((const float4*)xrow)[c4];
                xst[c4 * 4 + 0][lr] = v.x;
                xst[c4 * 4 + 1][lr] = v.y;
                xst[c4 * 4 + 2][lr] = v.z;
                xst[c4 * 4 + 3][lr] = v.w;
            }
        }
    }
    __syncthreads();

    const int j  = tid & 15;
    const int rt = tid >> 4;

    float4 acc[8];
    #pragma unroll
    for (int r = 0; r < 8; r++) acc[r] = make_float4(0.f, 0.f, 0.f, 0.f);

    #pragma unroll 4
    for (int k = 0; k < 64; k++) {
        const float4 w  = *(const float4*)&Ws[k * 64 + j * 4];
        const float4 xa = *(const float4*)&xst[k][rt * 8];
        const float4 xb = *(const float4*)&xst[k][rt * 8 + 4];
        acc[0].x += xa.x * w.x; acc[0].y += xa.x * w.y; acc[0].z += xa.x * w.z; acc[0].w += xa.x * w.w;
        acc[1].x += xa.y * w.x; acc[1].y += xa.y * w.y; acc[1].z += xa.y * w.z; acc[1].w += xa.y * w.w;
        acc[2].x += xa.z * w.x; acc[2].y += xa.z * w.y; acc[2].z += xa.z * w.z; acc[2].w += xa.z * w.w;
        acc[3].x += xa.w * w.x; acc[3].y += xa.w * w.y; acc[3].z += xa.w * w.z; acc[3].w += xa.w * w.w;
        acc[4].x += xb.x * w.x; acc[4].y += xb.x * w.y; acc[4].z += xb.x * w.z; acc[4].w += xb.x * w.w;
        acc[5].x += xb.y * w.x; acc[5].y += xb.y * w.y; acc[5].z += xb.y * w.z; acc[5].w += xb.y * w.w;
        acc[6].x += xb.z * w.x; acc[6].y += xb.z * w.y; acc[6].z += xb.z * w.z; acc[6].w += xb.z * w.w;
        acc[7].x += xb.w * w.x; acc[7].y += xb.w * w.y; acc[7].z += xb.w * w.z; acc[7].w += xb.w * w.w;
    }

    #pragma unroll
    for (int r = 0; r < 8; r++) {
        const int row = row0 + rt * 8 + r;
        if (row < N_TOT) {
            __half2 h0 = __floats2half2_rn(acc[r].x, acc[r].y);
            __half2 h1 = __floats2half2_rn(acc[r].z, acc[r].w);
            uint2 u = make_uint2(*(unsigned*)&h0, *(unsigned*)&h1);
            ((uint2*)(g_yh + (size_t)row * D))[j] = u;
        }
    }
}

// ---------------------------------------------------------------------------
// Fused edge pass: R9 16-lane shape (known-good), plus a 2-edge grid-stride
// unroll per group (4 row gathers in flight instead of 2). Same masks, same
// red.v4 pattern — MLP-only change.
// ---------------------------------------------------------------------------
__global__ void __launch_bounds__(256) edge_kernel(
    const int* __restrict__ ei, int E, float* __restrict__ out)
{
    const int lane = threadIdx.x & 31;
    const int li   = lane & 15;
    const unsigned mask = 0xFFFFu << ((lane >> 4) * 16);
    const int gid  = (blockIdx.x * blockDim.x + threadIdx.x) >> 4;
    const int ng   = (gridDim.x * blockDim.x) >> 4;

    float zloc = 0.0f;

    for (int e = gid; e < E; e += 2 * ng) {
        const int e2 = e + ng;
        const bool v2 = (e2 < E);

        const int src0 = __ldg(ei + e);
        const int dst0 = __ldg(ei + E + e);
        const int src1 = v2 ? __ldg(ei + e2) : src0;
        const int dst1 = v2 ? __ldg(ei + E + e2) : dst0;

        uint2 us0 = __ldg((const uint2*)(g_yh + (size_t)src0 * D) + li);
        uint2 ud0 = __ldg((const uint2*)(g_yh + (size_t)dst0 * D) + li);
        uint2 us1 = __ldg((const uint2*)(g_yh + (size_t)src1 * D) + li);
        uint2 ud1 = __ldg((const uint2*)(g_yh + (size_t)dst1 * D) + li);

        float2 s00 = __half22float2(*(__half2*)&us0.x);
        float2 s01 = __half22float2(*(__half2*)&us0.y);
        float2 d00 = __half22float2(*(__half2*)&ud0.x);
        float2 d01 = __half22float2(*(__half2*)&ud0.y);
        float2 s10 = __half22float2(*(__half2*)&us1.x);
        float2 s11 = __half22float2(*(__half2*)&us1.y);
        float2 d10 = __half22float2(*(__half2*)&ud1.x);
        float2 d11 = __half22float2(*(__half2*)&ud1.y);

        float t0 = s00.x * d00.x + s00.y * d00.y + s01.x * d01.x + s01.y * d01.y;
        float t1 = s10.x * d10.x + s10.y * d10.y + s11.x * d11.x + s11.y * d11.y;
        t0 += __shfl_xor_sync(mask, t0, 8);  t1 += __shfl_xor_sync(mask, t1, 8);
        t0 += __shfl_xor_sync(mask, t0, 4);  t1 += __shfl_xor_sync(mask, t1, 4);
        t0 += __shfl_xor_sync(mask, t0, 2);  t1 += __shfl_xor_sync(mask, t1, 2);
        t0 += __shfl_xor_sync(mask, t0, 1);  t1 += __shfl_xor_sync(mask, t1, 1);

        const float p0 = __expf(t0 >= 0.f ? t0 : 0.2f * t0);
        const float p1 = v2 ? __expf(t1 >= 0.f ? t1 : 0.2f * t1) : 0.f;
        if (li == 0) zloc += p0 + p1;

        float* dp0 = out + (size_t)dst0 * D + li * 4;
        asm volatile("red.global.add.v4.f32 [%0], {%1,%2,%3,%4};"
                     :: "l"(dp0), "f"(p0 * s00.x), "f"(p0 * s00.y),
                        "f"(p0 * s01.x), "f"(p0 * s01.y)
                     : "memory");
        if (v2) {
            float* dp1 = out + (size_t)dst1 * D + li * 4;
            asm volatile("red.global.add.v4.f32 [%0], {%1,%2,%3,%4};"
                         :: "l"(dp1), "f"(p1 * s10.x), "f"(p1 * s10.y),
                            "f"(p1 * s11.x), "f"(p1 * s11.y)
                         : "memory");
        }
    }

    // block-reduce zloc -> one atomic per block (loop done; full mask safe)
    float z = zloc;
    #pragma unroll
    for (int o = 16; o > 0; o >>= 1) z += __shfl_xor_sync(0xffffffffu, z, o);
    __shared__ float sz[8];
    if (lane == 0) sz[threadIdx.x >> 5] = z;
    __syncthreads();
    if (threadIdx.x == 0) {
        float s = 0.f;
        #pragma unroll
        for (int w = 0; w < 8; w++) s += sz[w];
        atomicAdd(&g_Z, s);
    }
}

// ---------------------------------------------------------------------------
// finalize: out = relu(out) / Z
// ---------------------------------------------------------------------------
__global__ void __launch_bounds__(256) finalize_kernel(float* __restrict__ out, int n)
{
    const float invZ = 1.0f / g_Z;
    const int n4 = n >> 2;
    float4* o4 = (float4*)out;
    const int st = gridDim.x * blockDim.x;
    for (int i = blockIdx.x * blockDim.x + threadIdx.x; i < n4; i += st) {
        float4 v = o4[i];
        v.x = v.x > 0.f ? v.x * invZ : 0.f;
        v.y = v.y > 0.f ? v.y * invZ : 0.f;
        v.z = v.z > 0.f ? v.z * invZ : 0.f;
        v.w = v.w > 0.f ? v.w * invZ : 0.f;
        o4[i] = v;
    }
}

// ---------------------------------------------------------------------------
// Launch: memset(out) on side stream ∥ build_y (also zeroes Z); join; edge;
// finalize.
// ---------------------------------------------------------------------------
extern "C" void kernel_launch(void* const* d_in, const int* in_sizes, int n_in,
                              void* d_out, int out_size)
{
    const int*   uidx = (const int*)d_in[0];
    const int*   iidx = (const int*)d_in[1];
    const int*   ei   = (const int*)d_in[2];
    const float* ut   = (const float*)d_in[5];
    const float* et   = (const float*)d_in[6];
    const float* W    = (const float*)d_in[7];
    float* out = (float*)d_out;
    const int E = in_sizes[2] / 2;

    static cudaStream_t s2 = nullptr;
    static cudaEvent_t ev_fork = nullptr, ev_join = nullptr;
    if (s2 == nullptr) {
        cudaStreamCreateWithFlags(&s2, cudaStreamNonBlocking);
        cudaEventCreateWithFlags(&ev_fork, cudaEventDisableTiming);
        cudaEventCreateWithFlags(&ev_join, cudaEventDisableTiming);
    }

    cudaEventRecord(ev_fork, 0);
    cudaStreamWaitEvent(s2, ev_fork, 0);
    cudaMemsetAsync(out, 0, (size_t)out_size * sizeof(float), s2);
    cudaEventRecord(ev_join, s2);

    build_y_kernel<<<(N_TOT + 127) / 128, 256>>>(uidx, iidx, ut, et, W);

    cudaStreamWaitEvent(0, ev_join, 0);
    edge_kernel<<<1184, 256>>>(ei, E, out);
    finalize_kernel<<<1184, 256>>>(out, out_size);
}